// round 8
// baseline (speedup 1.0000x reference)
#include <cuda_runtime.h>

#define Bsz 4096
#define Lsz 512
#define Msz 17
#define Hsz 17
#define Tch 4
#define NCHUNK (Lsz / Tch)          // 128
#define BLOCK_B 28
#define NTHREADS (BLOCK_B * Hsz)    // 476
#define NBLOCKS ((Bsz + BLOCK_B - 1) / BLOCK_B)  // 147

typedef unsigned long long u64;

__device__ __forceinline__ u64 pk2(float a, float b) {
    u64 r; asm("mov.b64 %0, {%1, %2};" : "=l"(r) : "f"(a), "f"(b)); return r;
}
__device__ __forceinline__ void upk2(u64 v, float &a, float &b) {
    asm("mov.b64 {%0, %1}, %2;" : "=f"(a), "=f"(b) : "l"(v));
}
__device__ __forceinline__ void ffma2(u64 &d, u64 a, u64 b) {
    asm("fma.rn.f32x2 %0, %1, %2, %0;" : "+l"(d) : "l"(a), "l"(b));
}
// single-MUFU tanh (sm_75+); sigmoids use 0.5+0.5*tanh(z/2) with the /2
// pre-folded into the gate weights, so they cost tanh + 1 FFMA.
__device__ __forceinline__ float tanh_ap(float z) {
    float r; asm("tanh.approx.f32 %0, %1;" : "=f"(r) : "f"(z)); return r;
}

__global__ __launch_bounds__(NTHREADS, 1) void lstm_fused_kernel(
    const float* __restrict__ x,
    const float* __restrict__ Wih,
    const float* __restrict__ Whh,
    const float* __restrict__ bih,
    const float* __restrict__ bhh,
    float* __restrict__ out)
{
    __shared__ u64 wih_if_s[Msz * Hsz];            // W_ih gate-pairs (i,f), PRE-HALVED
    __shared__ u64 wih_go_s[Msz * Hsz];            // W_ih gate-pairs (g, o/2)
    __shared__ u64 sx[BLOCK_B][Tch * Msz];         // x chunk, dup f32x2, idx k*4+t
    __shared__ float shp[2][BLOCK_B][20];          // h state, plain floats, dbl-buffered
    __shared__ float hbuf[BLOCK_B][2 * Tch * Hsz]; // 8-step h output ring

    const int tid = threadIdx.x;
    const int j = tid % Hsz;
    const int y = tid / Hsz;
    const int b = blockIdx.x * BLOCK_B + y;
    const bool act = (b < Bsz);
    const int bb = act ? b : (Bsz - 1);

    // ---- W_ih into smem, gate-pair packed; sigmoid gates (i,f,o) scaled by 0.5 ----
    if (tid < Msz * Hsz) {
        int k = tid / Hsz, jj = tid % Hsz;
        wih_if_s[tid] = pk2(0.5f * Wih[jj * Msz + k],
                            0.5f * Wih[(Hsz + jj) * Msz + k]);
        wih_go_s[tid] = pk2(Wih[(2 * Hsz + jj) * Msz + k],
                            0.5f * Wih[(3 * Hsz + jj) * Msz + k]);
    }

    // ---- W_hh in registers, natural pairs per gate; i,f,o rows pre-halved ----
    u64 wh0[9], wh1[9], wh2[9], wh3[9];
    {
        const float* w0 = Whh + (0 * Hsz + j) * Hsz;
        const float* w1 = Whh + (1 * Hsz + j) * Hsz;
        const float* w2 = Whh + (2 * Hsz + j) * Hsz;
        const float* w3 = Whh + (3 * Hsz + j) * Hsz;
#pragma unroll
        for (int p = 0; p < 8; p++) {
            wh0[p] = pk2(0.5f * w0[2 * p], 0.5f * w0[2 * p + 1]);
            wh1[p] = pk2(0.5f * w1[2 * p], 0.5f * w1[2 * p + 1]);
            wh2[p] = pk2(w2[2 * p],        w2[2 * p + 1]);
            wh3[p] = pk2(0.5f * w3[2 * p], 0.5f * w3[2 * p + 1]);
        }
        wh0[8] = pk2(0.5f * w0[16], 0.0f);
        wh1[8] = pk2(0.5f * w1[16], 0.0f);
        wh2[8] = pk2(w2[16],        0.0f);
        wh3[8] = pk2(0.5f * w3[16], 0.0f);
    }
    const u64 b_if = pk2(0.5f * (bih[j] + bhh[j]),
                         0.5f * (bih[Hsz + j] + bhh[Hsz + j]));
    const u64 b_go = pk2(bih[2 * Hsz + j] + bhh[2 * Hsz + j],
                         0.5f * (bih[3 * Hsz + j] + bhh[3 * Hsz + j]));

    const long OUT_ELEMS = (long)Bsz * Lsz * Hsz;
    const long H_OFF = OUT_ELEMS;
    const long C_OFF = OUT_ELEMS + (long)Bsz * Hsz;
    const long X_OFF = OUT_ELEMS + 2L * (long)Bsz * Hsz;

    const float4* xrow4 = (const float4*)(x + (long)bb * Lsz * Msz);
    float4*       xo4   = (float4*)(out + X_OFF + (long)bb * Lsz * Msz);
    float*        obase = out + (long)bb * Lsz * Hsz;

    shp[0][y][j] = 0.0f;
    shp[1][y][j] = 0.0f;
    if (j == 0) { shp[0][y][17] = 0.0f; shp[1][y][17] = 0.0f; }
    float c = 0.0f, hn = 0.0f;

    float4 v = xrow4[j];   // prefetch first x chunk

    for (int ch = 0; ch < NCHUNK; ch++) {
        const int t0 = ch * Tch;

        if (act) xo4[ch * Msz + j] = v;
        {
            float f[4] = {v.x, v.y, v.z, v.w};
            const int fbase = 4 * j;
#pragma unroll
            for (int i = 0; i < 4; i++) {
                int fi = fbase + i;
                int t = fi / Msz, k = fi - Msz * t;
                sx[y][k * Tch + t] = pk2(f[i], f[i]);
            }
        }
        if (ch + 1 < NCHUNK) v = xrow4[(ch + 1) * Msz + j];
        __syncthreads();

        // ---- 4-step x-projection burst ----
        u64 a_if[Tch], a_go[Tch];
#pragma unroll
        for (int t = 0; t < Tch; t++) { a_if[t] = b_if; a_go[t] = b_go; }
#pragma unroll
        for (int k = 0; k < Msz; k++) {
            const u64 wf = wih_if_s[k * Hsz + j];
            const u64 wg = wih_go_s[k * Hsz + j];
            const ulonglong2 x01 = ((const ulonglong2*)&sx[y][k * Tch])[0];
            const ulonglong2 x23 = ((const ulonglong2*)&sx[y][k * Tch])[1];
            ffma2(a_if[0], wf, x01.x); ffma2(a_go[0], wg, x01.x);
            ffma2(a_if[1], wf, x01.y); ffma2(a_go[1], wg, x01.y);
            ffma2(a_if[2], wf, x23.x); ffma2(a_go[2], wg, x23.x);
            ffma2(a_if[3], wf, x23.y); ffma2(a_go[3], wg, x23.y);
        }

        // ---- 4 recurrence steps ----
#pragma unroll
        for (int tl = 0; tl < Tch; tl++) {
            const int t = t0 + tl;
            const int cur = t & 1, nxt = cur ^ 1;

            u64 hc0 = 0ULL, hc1 = 0ULL, hc2 = 0ULL, hc3 = 0ULL;
            const u64* hp = (const u64*)shp[cur][y];
#pragma unroll
            for (int p = 0; p < 9; p++) {
                const u64 hv = hp[p];          // LDS.64 broadcast
                ffma2(hc0, wh0[p], hv);
                ffma2(hc1, wh1[p], hv);
                ffma2(hc2, wh2[p], hv);
                ffma2(hc3, wh3[p], hv);
            }

            float xi, xf, xg, xo_;
            upk2(a_if[tl], xi, xf);
            upk2(a_go[tl], xg, xo_);
            float l, h;
            upk2(hc0, l, h); const float zi = xi + (l + h);   // pre-halved
            upk2(hc1, l, h); const float zf = xf + (l + h);   // pre-halved
            upk2(hc2, l, h); const float zg = xg + (l + h);
            upk2(hc3, l, h); const float zo = xo_ + (l + h);  // pre-halved

            const float ig = fmaf(0.5f, tanh_ap(zi), 0.5f);
            const float fg = fmaf(0.5f, tanh_ap(zf), 0.5f);
            const float gg = tanh_ap(zg);
            const float og = fmaf(0.5f, tanh_ap(zo), 0.5f);
            c  = fg * c + ig * gg;
            hn = og * tanh_ap(c);

            hbuf[y][(t & 7) * Hsz + j] = hn;
            shp[nxt][y][j] = hn;
            __syncthreads();
        }

        // ---- flush 4 steps of h (coalesced float4) ----
        if (act) {
            const int half = ch & 1;
            const float4 hv4 = ((const float4*)&hbuf[y][half * (Tch * Hsz)])[j];
            ((float4*)(obase + t0 * Hsz))[j] = hv4;
        }
    }

    if (act) {
        out[H_OFF + (long)b * Hsz + j] = hn;
        out[C_OFF + (long)b * Hsz + j] = c;
    }
}

extern "C" void kernel_launch(void* const* d_in, const int* in_sizes, int n_in,
                              void* d_out, int out_size) {
    const float* x   = (const float*)d_in[0];
    const float* Wih = (const float*)d_in[1];
    const float* Whh = (const float*)d_in[2];
    const float* bih = (const float*)d_in[3];
    const float* bhh = (const float*)d_in[4];
    float* out = (float*)d_out;
    (void)in_sizes; (void)n_in; (void)out_size;

    lstm_fused_kernel<<<NBLOCKS, NTHREADS>>>(x, Wih, Whh, bih, bhh, out);
}

// round 9
// speedup vs baseline: 1.0888x; 1.0888x over previous
#include <cuda_runtime.h>

#define Bsz 4096
#define Lsz 512
#define Msz 17
#define Hsz 17
#define Tch 4
#define NCHUNK (Lsz / Tch)          // 128
#define BLOCK_B 28
#define NTHREADS (BLOCK_B * Hsz)    // 476
#define NBLOCKS ((Bsz + BLOCK_B - 1) / BLOCK_B)  // 147

typedef unsigned long long u64;

__device__ __forceinline__ u64 pk2(float a, float b) {
    u64 r; asm("mov.b64 %0, {%1, %2};" : "=l"(r) : "f"(a), "f"(b)); return r;
}
__device__ __forceinline__ void upk2(u64 v, float &a, float &b) {
    asm("mov.b64 {%0, %1}, %2;" : "=f"(a), "=f"(b) : "l"(v));
}
__device__ __forceinline__ void ffma2(u64 &d, u64 a, u64 b) {
    asm("fma.rn.f32x2 %0, %1, %2, %0;" : "+l"(d) : "l"(a), "l"(b));
}
// single-MUFU tanh; sigmoids = 0.5 + 0.5*tanh(z/2) with /2 folded into weights
__device__ __forceinline__ float tanh_ap(float z) {
    float r; asm("tanh.approx.f32 %0, %1;" : "=f"(r) : "f"(z)); return r;
}

__global__ __launch_bounds__(NTHREADS, 1) void lstm_fused_kernel(
    const float* __restrict__ x,
    const float* __restrict__ Wih,
    const float* __restrict__ Whh,
    const float* __restrict__ bih,
    const float* __restrict__ bhh,
    float* __restrict__ out)
{
    // W_ih: (if-pair, go-pair) side by side -> one LDS.128 per k
    __shared__ __align__(16) ulonglong2 wih_s[Msz * Hsz];
    __shared__ __align__(16) u64 sx[BLOCK_B][Tch * Msz];   // x chunk, dup f32x2, idx k*4+t
    __shared__ __align__(16) float shp[2][BLOCK_B][20];    // h state, plain, dbl-buffered
    __shared__ __align__(16) float hbuf[BLOCK_B][2 * Tch * Hsz]; // 8-step h ring

    const int tid = threadIdx.x;
    const int j = tid % Hsz;
    const int y = tid / Hsz;
    const int b = blockIdx.x * BLOCK_B + y;
    const bool act = (b < Bsz);
    const int bb = act ? b : (Bsz - 1);

    // ---- W_ih into smem; sigmoid gates (i,f,o) pre-scaled by 0.5 ----
    if (tid < Msz * Hsz) {
        int k = tid / Hsz, jj = tid % Hsz;
        ulonglong2 w2;
        w2.x = pk2(0.5f * Wih[jj * Msz + k],
                   0.5f * Wih[(Hsz + jj) * Msz + k]);
        w2.y = pk2(Wih[(2 * Hsz + jj) * Msz + k],
                   0.5f * Wih[(3 * Hsz + jj) * Msz + k]);
        wih_s[tid] = w2;
    }

    // ---- W_hh in registers, natural pairs per gate; i,f,o rows pre-halved ----
    u64 wh0[9], wh1[9], wh2[9], wh3[9];
    {
        const float* w0 = Whh + (0 * Hsz + j) * Hsz;
        const float* w1 = Whh + (1 * Hsz + j) * Hsz;
        const float* w2 = Whh + (2 * Hsz + j) * Hsz;
        const float* w3 = Whh + (3 * Hsz + j) * Hsz;
#pragma unroll
        for (int p = 0; p < 8; p++) {
            wh0[p] = pk2(0.5f * w0[2 * p], 0.5f * w0[2 * p + 1]);
            wh1[p] = pk2(0.5f * w1[2 * p], 0.5f * w1[2 * p + 1]);
            wh2[p] = pk2(w2[2 * p],        w2[2 * p + 1]);
            wh3[p] = pk2(0.5f * w3[2 * p], 0.5f * w3[2 * p + 1]);
        }
        wh0[8] = pk2(0.5f * w0[16], 0.0f);
        wh1[8] = pk2(0.5f * w1[16], 0.0f);
        wh2[8] = pk2(w2[16],        0.0f);
        wh3[8] = pk2(0.5f * w3[16], 0.0f);
    }
    const u64 b_if = pk2(0.5f * (bih[j] + bhh[j]),
                         0.5f * (bih[Hsz + j] + bhh[Hsz + j]));
    const u64 b_go = pk2(bih[2 * Hsz + j] + bhh[2 * Hsz + j],
                         0.5f * (bih[3 * Hsz + j] + bhh[3 * Hsz + j]));

    const long OUT_ELEMS = (long)Bsz * Lsz * Hsz;
    const long H_OFF = OUT_ELEMS;
    const long C_OFF = OUT_ELEMS + (long)Bsz * Hsz;
    const long X_OFF = OUT_ELEMS + 2L * (long)Bsz * Hsz;

    const float4* xrow4 = (const float4*)(x + (long)bb * Lsz * Msz);
    float4*       xo4   = (float4*)(out + X_OFF + (long)bb * Lsz * Msz);
    float*        obase = out + (long)bb * Lsz * Hsz;

    shp[0][y][j] = 0.0f;
    shp[1][y][j] = 0.0f;
    if (j == 0) {
        shp[0][y][17] = 0.0f; shp[1][y][17] = 0.0f;
        shp[0][y][18] = 0.0f; shp[1][y][18] = 0.0f;
        shp[0][y][19] = 0.0f; shp[1][y][19] = 0.0f;
    }
    float c = 0.0f, hn = 0.0f;

    float4 v = xrow4[j];   // prefetch first x chunk

    for (int ch = 0; ch < NCHUNK; ch++) {
        const int t0 = ch * Tch;

        if (act) xo4[ch * Msz + j] = v;
        {
            float f[4] = {v.x, v.y, v.z, v.w};
            const int fbase = 4 * j;
#pragma unroll
            for (int i = 0; i < 4; i++) {
                int fi = fbase + i;
                int t = fi / Msz, k = fi - Msz * t;
                sx[y][k * Tch + t] = pk2(f[i], f[i]);
            }
        }
        if (ch + 1 < NCHUNK) v = xrow4[(ch + 1) * Msz + j];
        __syncthreads();

        // ---- 4-step x-projection burst: 1 LDS.128 weights + 2 LDS.128 x per k ----
        u64 a_if[Tch], a_go[Tch];
#pragma unroll
        for (int t = 0; t < Tch; t++) { a_if[t] = b_if; a_go[t] = b_go; }
#pragma unroll
        for (int k = 0; k < Msz; k++) {
            const ulonglong2 w2 = wih_s[k * Hsz + j];       // {if, go} pairs
            const ulonglong2 x01 = ((const ulonglong2*)&sx[y][k * Tch])[0];
            const ulonglong2 x23 = ((const ulonglong2*)&sx[y][k * Tch])[1];
            ffma2(a_if[0], w2.x, x01.x); ffma2(a_go[0], w2.y, x01.x);
            ffma2(a_if[1], w2.x, x01.y); ffma2(a_go[1], w2.y, x01.y);
            ffma2(a_if[2], w2.x, x23.x); ffma2(a_go[2], w2.y, x23.x);
            ffma2(a_if[3], w2.x, x23.y); ffma2(a_go[3], w2.y, x23.y);
        }

        // ---- 4 recurrence steps: h via 4xLDS.128 + 1xLDS.64 ----
#pragma unroll
        for (int tl = 0; tl < Tch; tl++) {
            const int t = t0 + tl;
            const int cur = t & 1, nxt = cur ^ 1;

            const ulonglong2* hp2 = (const ulonglong2*)shp[cur][y];
            const ulonglong2 q0 = hp2[0];
            const ulonglong2 q1 = hp2[1];
            const ulonglong2 q2 = hp2[2];
            const ulonglong2 q3 = hp2[3];
            const u64 q8 = ((const u64*)shp[cur][y])[8];    // (h16, pad)

            u64 hc0 = 0ULL, hc1 = 0ULL, hc2 = 0ULL, hc3 = 0ULL;
            ffma2(hc0, wh0[0], q0.x); ffma2(hc1, wh1[0], q0.x);
            ffma2(hc2, wh2[0], q0.x); ffma2(hc3, wh3[0], q0.x);
            ffma2(hc0, wh0[1], q0.y); ffma2(hc1, wh1[1], q0.y);
            ffma2(hc2, wh2[1], q0.y); ffma2(hc3, wh3[1], q0.y);
            ffma2(hc0, wh0[2], q1.x); ffma2(hc1, wh1[2], q1.x);
            ffma2(hc2, wh2[2], q1.x); ffma2(hc3, wh3[2], q1.x);
            ffma2(hc0, wh0[3], q1.y); ffma2(hc1, wh1[3], q1.y);
            ffma2(hc2, wh2[3], q1.y); ffma2(hc3, wh3[3], q1.y);
            ffma2(hc0, wh0[4], q2.x); ffma2(hc1, wh1[4], q2.x);
            ffma2(hc2, wh2[4], q2.x); ffma2(hc3, wh3[4], q2.x);
            ffma2(hc0, wh0[5], q2.y); ffma2(hc1, wh1[5], q2.y);
            ffma2(hc2, wh2[5], q2.y); ffma2(hc3, wh3[5], q2.y);
            ffma2(hc0, wh0[6], q3.x); ffma2(hc1, wh1[6], q3.x);
            ffma2(hc2, wh2[6], q3.x); ffma2(hc3, wh3[6], q3.x);
            ffma2(hc0, wh0[7], q3.y); ffma2(hc1, wh1[7], q3.y);
            ffma2(hc2, wh2[7], q3.y); ffma2(hc3, wh3[7], q3.y);
            ffma2(hc0, wh0[8], q8);   ffma2(hc1, wh1[8], q8);
            ffma2(hc2, wh2[8], q8);   ffma2(hc3, wh3[8], q8);

            float xi, xf, xg, xo_;
            upk2(a_if[tl], xi, xf);
            upk2(a_go[tl], xg, xo_);
            float l, h;
            upk2(hc0, l, h); const float zi = xi + (l + h);
            upk2(hc1, l, h); const float zf = xf + (l + h);
            upk2(hc2, l, h); const float zg = xg + (l + h);
            upk2(hc3, l, h); const float zo = xo_ + (l + h);

            const float ig = fmaf(0.5f, tanh_ap(zi), 0.5f);
            const float fg = fmaf(0.5f, tanh_ap(zf), 0.5f);
            const float gg = tanh_ap(zg);
            const float og = fmaf(0.5f, tanh_ap(zo), 0.5f);
            c  = fg * c + ig * gg;
            hn = og * tanh_ap(c);

            hbuf[y][(t & 7) * Hsz + j] = hn;
            shp[nxt][y][j] = hn;
            __syncthreads();
        }

        // ---- flush 4 steps of h (coalesced float4) ----
        if (act) {
            const int half = ch & 1;
            const float4 hv4 = ((const float4*)&hbuf[y][half * (Tch * Hsz)])[j];
            ((float4*)(obase + t0 * Hsz))[j] = hv4;
        }
    }

    if (act) {
        out[H_OFF + (long)b * Hsz + j] = hn;
        out[C_OFF + (long)b * Hsz + j] = c;
    }
}

extern "C" void kernel_launch(void* const* d_in, const int* in_sizes, int n_in,
                              void* d_out, int out_size) {
    const float* x   = (const float*)d_in[0];
    const float* Wih = (const float*)d_in[1];
    const float* Whh = (const float*)d_in[2];
    const float* bih = (const float*)d_in[3];
    const float* bhh = (const float*)d_in[4];
    float* out = (float*)d_out;
    (void)in_sizes; (void)n_in; (void)out_size;

    lstm_fused_kernel<<<NBLOCKS, NTHREADS>>>(x, Wih, Whh, bih, bhh, out);
}

// round 10
// speedup vs baseline: 1.3778x; 1.2654x over previous
#include <cuda_runtime.h>

#define Bsz 4096
#define Lsz 512
#define Msz 17
#define Hsz 17
#define Tch 4
#define NCHUNK (Lsz / Tch)          // 128
#define BLOCK_B 28
#define NTHREADS (BLOCK_B * Hsz)    // 476
#define NBLOCKS ((Bsz + BLOCK_B - 1) / BLOCK_B)  // 147

typedef unsigned long long u64;

__device__ __forceinline__ u64 pk2(float a, float b) {
    u64 r; asm("mov.b64 %0, {%1, %2};" : "=l"(r) : "f"(a), "f"(b)); return r;
}
__device__ __forceinline__ void upk2(u64 v, float &a, float &b) {
    asm("mov.b64 {%0, %1}, %2;" : "=f"(a), "=f"(b) : "l"(v));
}
__device__ __forceinline__ void ffma2(u64 &d, u64 a, u64 b) {
    asm("fma.rn.f32x2 %0, %1, %2, %0;" : "+l"(d) : "l"(a), "l"(b));
}
// single-MUFU tanh; sigmoids = 0.5 + 0.5*tanh(z/2) with /2 folded into weights
__device__ __forceinline__ float tanh_ap(float z) {
    float r; asm("tanh.approx.f32 %0, %1;" : "=f"(r) : "f"(z)); return r;
}

__global__ __launch_bounds__(NTHREADS, 1) void lstm_fused_kernel(
    const float* __restrict__ x,
    const float* __restrict__ Wih,
    const float* __restrict__ Whh,
    const float* __restrict__ bih,
    const float* __restrict__ bhh,
    float* __restrict__ out)
{
    // W_ih: (if-pair, go-pair) side by side -> one LDS.128 per k
    __shared__ __align__(16) ulonglong2 wih_s[Msz * Hsz];
    // x chunk, PLAIN floats, layout [k][t]: sx[y][k*4+t]; 68 floats/row (16B-mult)
    __shared__ __align__(16) float sx[BLOCK_B][Tch * Msz];
    __shared__ __align__(16) float shp[2][BLOCK_B][20];    // h state, plain, dbl-buffered
    __shared__ __align__(16) float hbuf[BLOCK_B][2 * Tch * Hsz]; // 8-step h ring

    const int tid = threadIdx.x;
    const int j = tid % Hsz;
    const int y = tid / Hsz;
    const int b = blockIdx.x * BLOCK_B + y;
    const bool act = (b < Bsz);
    const int bb = act ? b : (Bsz - 1);

    // ---- W_ih into smem; sigmoid gates (i,f,o) pre-scaled by 0.5 ----
    if (tid < Msz * Hsz) {
        int k = tid / Hsz, jj = tid % Hsz;
        ulonglong2 w2;
        w2.x = pk2(0.5f * Wih[jj * Msz + k],
                   0.5f * Wih[(Hsz + jj) * Msz + k]);
        w2.y = pk2(Wih[(2 * Hsz + jj) * Msz + k],
                   0.5f * Wih[(3 * Hsz + jj) * Msz + k]);
        wih_s[tid] = w2;
    }

    // ---- W_hh in registers, natural pairs per gate; i,f,o rows pre-halved ----
    u64 wh0[9], wh1[9], wh2[9], wh3[9];
    {
        const float* w0 = Whh + (0 * Hsz + j) * Hsz;
        const float* w1 = Whh + (1 * Hsz + j) * Hsz;
        const float* w2 = Whh + (2 * Hsz + j) * Hsz;
        const float* w3 = Whh + (3 * Hsz + j) * Hsz;
#pragma unroll
        for (int p = 0; p < 8; p++) {
            wh0[p] = pk2(0.5f * w0[2 * p], 0.5f * w0[2 * p + 1]);
            wh1[p] = pk2(0.5f * w1[2 * p], 0.5f * w1[2 * p + 1]);
            wh2[p] = pk2(w2[2 * p],        w2[2 * p + 1]);
            wh3[p] = pk2(0.5f * w3[2 * p], 0.5f * w3[2 * p + 1]);
        }
        wh0[8] = pk2(0.5f * w0[16], 0.0f);
        wh1[8] = pk2(0.5f * w1[16], 0.0f);
        wh2[8] = pk2(w2[16],        0.0f);
        wh3[8] = pk2(0.5f * w3[16], 0.0f);
    }
    const u64 b_if = pk2(0.5f * (bih[j] + bhh[j]),
                         0.5f * (bih[Hsz + j] + bhh[Hsz + j]));
    const u64 b_go = pk2(bih[2 * Hsz + j] + bhh[2 * Hsz + j],
                         0.5f * (bih[3 * Hsz + j] + bhh[3 * Hsz + j]));

    const long OUT_ELEMS = (long)Bsz * Lsz * Hsz;
    const long H_OFF = OUT_ELEMS;
    const long C_OFF = OUT_ELEMS + (long)Bsz * Hsz;
    const long X_OFF = OUT_ELEMS + 2L * (long)Bsz * Hsz;

    const float4* xrow4 = (const float4*)(x + (long)bb * Lsz * Msz);
    float4*       xo4   = (float4*)(out + X_OFF + (long)bb * Lsz * Msz);
    float*        obase = out + (long)bb * Lsz * Hsz;

    shp[0][y][j] = 0.0f;
    shp[1][y][j] = 0.0f;
    if (j == 0) {
        shp[0][y][17] = 0.0f; shp[1][y][17] = 0.0f;
        shp[0][y][18] = 0.0f; shp[1][y][18] = 0.0f;
        shp[0][y][19] = 0.0f; shp[1][y][19] = 0.0f;
    }
    float c = 0.0f, hn = 0.0f;

    float4 v = xrow4[j];   // prefetch first x chunk

    for (int ch = 0; ch < NCHUNK; ch++) {
        const int t0 = ch * Tch;

        if (act) xo4[ch * Msz + j] = v;
        {
            float f[4] = {v.x, v.y, v.z, v.w};
            const int fbase = 4 * j;
#pragma unroll
            for (int i = 0; i < 4; i++) {
                int fi = fbase + i;                 // chunk index = t*17 + k
                int t = fi / Msz, k = fi - Msz * t;
                sx[y][k * Tch + t] = f[i];          // plain STS.32
            }
        }
        if (ch + 1 < NCHUNK) v = xrow4[(ch + 1) * Msz + j];
        __syncthreads();

        // ---- 4-step x-projection burst: per k, 1 LDS.128 x + 1 LDS.128 w ----
        u64 a_if[Tch], a_go[Tch];
#pragma unroll
        for (int t = 0; t < Tch; t++) { a_if[t] = b_if; a_go[t] = b_go; }
#pragma unroll
        for (int k = 0; k < Msz; k++) {
            const ulonglong2 w2 = wih_s[k * Hsz + j];          // {if, go} pairs
            const float4 xf = *(const float4*)&sx[y][k * Tch]; // x_t0..x_t3 plain
            const u64 d0 = pk2(xf.x, xf.x);
            const u64 d1 = pk2(xf.y, xf.y);
            const u64 d2 = pk2(xf.z, xf.z);
            const u64 d3 = pk2(xf.w, xf.w);
            ffma2(a_if[0], w2.x, d0); ffma2(a_go[0], w2.y, d0);
            ffma2(a_if[1], w2.x, d1); ffma2(a_go[1], w2.y, d1);
            ffma2(a_if[2], w2.x, d2); ffma2(a_go[2], w2.y, d2);
            ffma2(a_if[3], w2.x, d3); ffma2(a_go[3], w2.y, d3);
        }

        // ---- 4 recurrence steps: h via 4xLDS.128 + 1xLDS.64 ----
#pragma unroll
        for (int tl = 0; tl < Tch; tl++) {
            const int t = t0 + tl;
            const int cur = t & 1, nxt = cur ^ 1;

            const ulonglong2* hp2 = (const ulonglong2*)shp[cur][y];
            const ulonglong2 q0 = hp2[0];
            const ulonglong2 q1 = hp2[1];
            const ulonglong2 q2 = hp2[2];
            const ulonglong2 q3 = hp2[3];
            const u64 q8 = ((const u64*)shp[cur][y])[8];    // (h16, pad)

            u64 hc0 = 0ULL, hc1 = 0ULL, hc2 = 0ULL, hc3 = 0ULL;
            ffma2(hc0, wh0[0], q0.x); ffma2(hc1, wh1[0], q0.x);
            ffma2(hc2, wh2[0], q0.x); ffma2(hc3, wh3[0], q0.x);
            ffma2(hc0, wh0[1], q0.y); ffma2(hc1, wh1[1], q0.y);
            ffma2(hc2, wh2[1], q0.y); ffma2(hc3, wh3[1], q0.y);
            ffma2(hc0, wh0[2], q1.x); ffma2(hc1, wh1[2], q1.x);
            ffma2(hc2, wh2[2], q1.x); ffma2(hc3, wh3[2], q1.x);
            ffma2(hc0, wh0[3], q1.y); ffma2(hc1, wh1[3], q1.y);
            ffma2(hc2, wh2[3], q1.y); ffma2(hc3, wh3[3], q1.y);
            ffma2(hc0, wh0[4], q2.x); ffma2(hc1, wh1[4], q2.x);
            ffma2(hc2, wh2[4], q2.x); ffma2(hc3, wh3[4], q2.x);
            ffma2(hc0, wh0[5], q2.y); ffma2(hc1, wh1[5], q2.y);
            ffma2(hc2, wh2[5], q2.y); ffma2(hc3, wh3[5], q2.y);
            ffma2(hc0, wh0[6], q3.x); ffma2(hc1, wh1[6], q3.x);
            ffma2(hc2, wh2[6], q3.x); ffma2(hc3, wh3[6], q3.x);
            ffma2(hc0, wh0[7], q3.y); ffma2(hc1, wh1[7], q3.y);
            ffma2(hc2, wh2[7], q3.y); ffma2(hc3, wh3[7], q3.y);
            ffma2(hc0, wh0[8], q8);   ffma2(hc1, wh1[8], q8);
            ffma2(hc2, wh2[8], q8);   ffma2(hc3, wh3[8], q8);

            float xi, xf_, xg, xo_;
            upk2(a_if[tl], xi, xf_);
            upk2(a_go[tl], xg, xo_);
            float l, h;
            upk2(hc0, l, h); const float zi = xi + (l + h);
            upk2(hc1, l, h); const float zf = xf_ + (l + h);
            upk2(hc2, l, h); const float zg = xg + (l + h);
            upk2(hc3, l, h); const float zo = xo_ + (l + h);

            const float ig = fmaf(0.5f, tanh_ap(zi), 0.5f);
            const float fg = fmaf(0.5f, tanh_ap(zf), 0.5f);
            const float gg = tanh_ap(zg);
            const float og = fmaf(0.5f, tanh_ap(zo), 0.5f);
            c  = fg * c + ig * gg;
            hn = og * tanh_ap(c);

            hbuf[y][(t & 7) * Hsz + j] = hn;
            shp[nxt][y][j] = hn;
            __syncthreads();
        }

        // ---- flush 4 steps of h (coalesced float4) ----
        if (act) {
            const int half = ch & 1;
            const float4 hv4 = ((const float4*)&hbuf[y][half * (Tch * Hsz)])[j];
            ((float4*)(obase + t0 * Hsz))[j] = hv4;
        }
    }

    if (act) {
        out[H_OFF + (long)b * Hsz + j] = hn;
        out[C_OFF + (long)b * Hsz + j] = c;
    }
}

extern "C" void kernel_launch(void* const* d_in, const int* in_sizes, int n_in,
                              void* d_out, int out_size) {
    const float* x   = (const float*)d_in[0];
    const float* Wih = (const float*)d_in[1];
    const float* Whh = (const float*)d_in[2];
    const float* bih = (const float*)d_in[3];
    const float* bhh = (const float*)d_in[4];
    float* out = (float*)d_out;
    (void)in_sizes; (void)n_in; (void)out_size;

    lstm_fused_kernel<<<NBLOCKS, NTHREADS>>>(x, Wih, Whh, bih, bhh, out);
}

// round 11
// speedup vs baseline: 1.4336x; 1.0405x over previous
#include <cuda_runtime.h>

#define Bsz 4096
#define Lsz 512
#define Msz 17
#define Hsz 17
#define Tch 4
#define NCHUNK (Lsz / Tch)          // 128
#define BLOCK_B 14
#define NTHREADS (BLOCK_B * Hsz)    // 238  -> 2 blocks/SM
#define NBLOCKS ((Bsz + BLOCK_B - 1) / BLOCK_B)  // 293

typedef unsigned long long u64;

__device__ __forceinline__ u64 pk2(float a, float b) {
    u64 r; asm("mov.b64 %0, {%1, %2};" : "=l"(r) : "f"(a), "f"(b)); return r;
}
__device__ __forceinline__ void upk2(u64 v, float &a, float &b) {
    asm("mov.b64 {%0, %1}, %2;" : "=f"(a), "=f"(b) : "l"(v));
}
__device__ __forceinline__ void ffma2(u64 &d, u64 a, u64 b) {
    asm("fma.rn.f32x2 %0, %1, %2, %0;" : "+l"(d) : "l"(a), "l"(b));
}
// single-MUFU tanh; sigmoids = 0.5 + 0.5*tanh(z/2) with /2 folded into weights
__device__ __forceinline__ float tanh_ap(float z) {
    float r; asm("tanh.approx.f32 %0, %1;" : "=f"(r) : "f"(z)); return r;
}

__global__ __launch_bounds__(NTHREADS, 2) void lstm_fused_kernel(
    const float* __restrict__ x,
    const float* __restrict__ Wih,
    const float* __restrict__ Whh,
    const float* __restrict__ bih,
    const float* __restrict__ bhh,
    float* __restrict__ out)
{
    // W_ih: (if-pair, go-pair) side by side -> one LDS.128 per k
    __shared__ __align__(16) ulonglong2 wih_s[Msz * Hsz];
    // x chunk, PLAIN floats, layout [k][t]: sx[y][k*4+t]
    __shared__ __align__(16) float sx[BLOCK_B][Tch * Msz];
    __shared__ __align__(16) float shp[2][BLOCK_B][20];    // h state, plain, dbl-buffered
    __shared__ __align__(16) float hbuf[BLOCK_B][2 * Tch * Hsz]; // 8-step h ring

    const int tid = threadIdx.x;
    const int j = tid % Hsz;
    const int y = tid / Hsz;
    const int b = blockIdx.x * BLOCK_B + y;
    const bool act = (b < Bsz);
    const int bb = act ? b : (Bsz - 1);

    // ---- W_ih into smem; sigmoid gates (i,f,o) pre-scaled by 0.5 ----
    for (int idx = tid; idx < Msz * Hsz; idx += NTHREADS) {
        int k = idx / Hsz, jj = idx % Hsz;
        ulonglong2 w2;
        w2.x = pk2(0.5f * Wih[jj * Msz + k],
                   0.5f * Wih[(Hsz + jj) * Msz + k]);
        w2.y = pk2(Wih[(2 * Hsz + jj) * Msz + k],
                   0.5f * Wih[(3 * Hsz + jj) * Msz + k]);
        wih_s[idx] = w2;
    }

    // ---- W_hh in registers, natural pairs per gate; i,f,o rows pre-halved ----
    u64 wh0[9], wh1[9], wh2[9], wh3[9];
    {
        const float* w0 = Whh + (0 * Hsz + j) * Hsz;
        const float* w1 = Whh + (1 * Hsz + j) * Hsz;
        const float* w2 = Whh + (2 * Hsz + j) * Hsz;
        const float* w3 = Whh + (3 * Hsz + j) * Hsz;
#pragma unroll
        for (int p = 0; p < 8; p++) {
            wh0[p] = pk2(0.5f * w0[2 * p], 0.5f * w0[2 * p + 1]);
            wh1[p] = pk2(0.5f * w1[2 * p], 0.5f * w1[2 * p + 1]);
            wh2[p] = pk2(w2[2 * p],        w2[2 * p + 1]);
            wh3[p] = pk2(0.5f * w3[2 * p], 0.5f * w3[2 * p + 1]);
        }
        wh0[8] = pk2(0.5f * w0[16], 0.0f);
        wh1[8] = pk2(0.5f * w1[16], 0.0f);
        wh2[8] = pk2(w2[16],        0.0f);
        wh3[8] = pk2(0.5f * w3[16], 0.0f);
    }
    const u64 b_if = pk2(0.5f * (bih[j] + bhh[j]),
                         0.5f * (bih[Hsz + j] + bhh[Hsz + j]));
    const u64 b_go = pk2(bih[2 * Hsz + j] + bhh[2 * Hsz + j],
                         0.5f * (bih[3 * Hsz + j] + bhh[3 * Hsz + j]));

    const long OUT_ELEMS = (long)Bsz * Lsz * Hsz;
    const long H_OFF = OUT_ELEMS;
    const long C_OFF = OUT_ELEMS + (long)Bsz * Hsz;
    const long X_OFF = OUT_ELEMS + 2L * (long)Bsz * Hsz;

    const float4* xrow4 = (const float4*)(x + (long)bb * Lsz * Msz);
    float4*       xo4   = (float4*)(out + X_OFF + (long)bb * Lsz * Msz);
    float*        obase = out + (long)bb * Lsz * Hsz;

    shp[0][y][j] = 0.0f;
    shp[1][y][j] = 0.0f;
    if (j == 0) {
        shp[0][y][17] = 0.0f; shp[1][y][17] = 0.0f;
        shp[0][y][18] = 0.0f; shp[1][y][18] = 0.0f;
        shp[0][y][19] = 0.0f; shp[1][y][19] = 0.0f;
    }
    float c = 0.0f, hn = 0.0f;

    float4 v = xrow4[j];   // prefetch first x chunk

    for (int ch = 0; ch < NCHUNK; ch++) {
        const int t0 = ch * Tch;

        if (act) xo4[ch * Msz + j] = v;
        {
            float f[4] = {v.x, v.y, v.z, v.w};
            const int fbase = 4 * j;
#pragma unroll
            for (int i = 0; i < 4; i++) {
                int fi = fbase + i;                 // chunk index = t*17 + k
                int t = fi / Msz, k = fi - Msz * t;
                sx[y][k * Tch + t] = f[i];          // plain STS.32
            }
        }
        if (ch + 1 < NCHUNK) v = xrow4[(ch + 1) * Msz + j];
        __syncthreads();

        // ---- 4-step x-projection burst: per k, 1 LDS.128 x + 1 LDS.128 w ----
        u64 a_if[Tch], a_go[Tch];
#pragma unroll
        for (int t = 0; t < Tch; t++) { a_if[t] = b_if; a_go[t] = b_go; }
#pragma unroll
        for (int k = 0; k < Msz; k++) {
            const ulonglong2 w2 = wih_s[k * Hsz + j];          // {if, go} pairs
            const float4 xf = *(const float4*)&sx[y][k * Tch]; // x_t0..x_t3 plain
            const u64 d0 = pk2(xf.x, xf.x);
            const u64 d1 = pk2(xf.y, xf.y);
            const u64 d2 = pk2(xf.z, xf.z);
            const u64 d3 = pk2(xf.w, xf.w);
            ffma2(a_if[0], w2.x, d0); ffma2(a_go[0], w2.y, d0);
            ffma2(a_if[1], w2.x, d1); ffma2(a_go[1], w2.y, d1);
            ffma2(a_if[2], w2.x, d2); ffma2(a_go[2], w2.y, d2);
            ffma2(a_if[3], w2.x, d3); ffma2(a_go[3], w2.y, d3);
        }

        // ---- 4 recurrence steps: h via 4xLDS.128 + 1xLDS.64 ----
#pragma unroll
        for (int tl = 0; tl < Tch; tl++) {
            const int t = t0 + tl;
            const int cur = t & 1, nxt = cur ^ 1;

            const ulonglong2* hp2 = (const ulonglong2*)shp[cur][y];
            const ulonglong2 q0 = hp2[0];
            const ulonglong2 q1 = hp2[1];
            const ulonglong2 q2 = hp2[2];
            const ulonglong2 q3 = hp2[3];
            const u64 q8 = ((const u64*)shp[cur][y])[8];    // (h16, pad)

            u64 hc0 = 0ULL, hc1 = 0ULL, hc2 = 0ULL, hc3 = 0ULL;
            ffma2(hc0, wh0[0], q0.x); ffma2(hc1, wh1[0], q0.x);
            ffma2(hc2, wh2[0], q0.x); ffma2(hc3, wh3[0], q0.x);
            ffma2(hc0, wh0[1], q0.y); ffma2(hc1, wh1[1], q0.y);
            ffma2(hc2, wh2[1], q0.y); ffma2(hc3, wh3[1], q0.y);
            ffma2(hc0, wh0[2], q1.x); ffma2(hc1, wh1[2], q1.x);
            ffma2(hc2, wh2[2], q1.x); ffma2(hc3, wh3[2], q1.x);
            ffma2(hc0, wh0[3], q1.y); ffma2(hc1, wh1[3], q1.y);
            ffma2(hc2, wh2[3], q1.y); ffma2(hc3, wh3[3], q1.y);
            ffma2(hc0, wh0[4], q2.x); ffma2(hc1, wh1[4], q2.x);
            ffma2(hc2, wh2[4], q2.x); ffma2(hc3, wh3[4], q2.x);
            ffma2(hc0, wh0[5], q2.y); ffma2(hc1, wh1[5], q2.y);
            ffma2(hc2, wh2[5], q2.y); ffma2(hc3, wh3[5], q2.y);
            ffma2(hc0, wh0[6], q3.x); ffma2(hc1, wh1[6], q3.x);
            ffma2(hc2, wh2[6], q3.x); ffma2(hc3, wh3[6], q3.x);
            ffma2(hc0, wh0[7], q3.y); ffma2(hc1, wh1[7], q3.y);
            ffma2(hc2, wh2[7], q3.y); ffma2(hc3, wh3[7], q3.y);
            ffma2(hc0, wh0[8], q8);   ffma2(hc1, wh1[8], q8);
            ffma2(hc2, wh2[8], q8);   ffma2(hc3, wh3[8], q8);

            float xi, xf_, xg, xo_;
            upk2(a_if[tl], xi, xf_);
            upk2(a_go[tl], xg, xo_);
            float l, h;
            upk2(hc0, l, h); const float zi = xi + (l + h);
            upk2(hc1, l, h); const float zf = xf_ + (l + h);
            upk2(hc2, l, h); const float zg = xg + (l + h);
            upk2(hc3, l, h); const float zo = xo_ + (l + h);

            const float ig = fmaf(0.5f, tanh_ap(zi), 0.5f);
            const float fg = fmaf(0.5f, tanh_ap(zf), 0.5f);
            const float gg = tanh_ap(zg);
            const float og = fmaf(0.5f, tanh_ap(zo), 0.5f);
            c  = fg * c + ig * gg;
            hn = og * tanh_ap(c);

            hbuf[y][(t & 7) * Hsz + j] = hn;
            shp[nxt][y][j] = hn;
            __syncthreads();
        }

        // ---- flush 4 steps of h (coalesced float4) ----
        if (act) {
            const int half = ch & 1;
            const float4 hv4 = ((const float4*)&hbuf[y][half * (Tch * Hsz)])[j];
            ((float4*)(obase + t0 * Hsz))[j] = hv4;
        }
    }

    if (act) {
        out[H_OFF + (long)b * Hsz + j] = hn;
        out[C_OFF + (long)b * Hsz + j] = c;
    }
}

extern "C" void kernel_launch(void* const* d_in, const int* in_sizes, int n_in,
                              void* d_out, int out_size) {
    const float* x   = (const float*)d_in[0];
    const float* Wih = (const float*)d_in[1];
    const float* Whh = (const float*)d_in[2];
    const float* bih = (const float*)d_in[3];
    const float* bhh = (const float*)d_in[4];
    float* out = (float*)d_out;
    (void)in_sizes; (void)n_in; (void)out_size;

    lstm_fused_kernel<<<NBLOCKS, NTHREADS>>>(x, Wih, Whh, bih, bhh, out);
}

// round 12
// speedup vs baseline: 1.4705x; 1.0258x over previous
#include <cuda_runtime.h>

#define Bsz 4096
#define Lsz 512
#define Msz 17
#define Hsz 17
#define Tch 8
#define NCHUNK (Lsz / Tch)          // 64
#define BLOCK_B 14
#define NTHREADS (BLOCK_B * Hsz)    // 238  -> 2 blocks/SM
#define NBLOCKS ((Bsz + BLOCK_B - 1) / BLOCK_B)  // 293
#define CHUNK_F4 (2 * Msz)          // 34 float4 per row-chunk (136 floats)

typedef unsigned long long u64;

__device__ __forceinline__ u64 pk2(float a, float b) {
    u64 r; asm("mov.b64 %0, {%1, %2};" : "=l"(r) : "f"(a), "f"(b)); return r;
}
__device__ __forceinline__ void upk2(u64 v, float &a, float &b) {
    asm("mov.b64 {%0, %1}, %2;" : "=f"(a), "=f"(b) : "l"(v));
}
__device__ __forceinline__ void ffma2(u64 &d, u64 a, u64 b) {
    asm("fma.rn.f32x2 %0, %1, %2, %0;" : "+l"(d) : "l"(a), "l"(b));
}
// single-MUFU tanh; sigmoids = 0.5 + 0.5*tanh(z/2) with /2 folded into weights
__device__ __forceinline__ float tanh_ap(float z) {
    float r; asm("tanh.approx.f32 %0, %1;" : "=f"(r) : "f"(z)); return r;
}

__global__ __launch_bounds__(NTHREADS, 2) void lstm_fused_kernel(
    const float* __restrict__ x,
    const float* __restrict__ Wih,
    const float* __restrict__ Whh,
    const float* __restrict__ bih,
    const float* __restrict__ bhh,
    float* __restrict__ out)
{
    // W_ih: (if-pair, go-pair) side by side -> one LDS.128 per k per chunk
    __shared__ __align__(16) ulonglong2 wih_s[Msz * Hsz];
    // x chunk, PLAIN floats, layout [k][t]: sx[y][k*8+t]; 136 floats/row
    __shared__ __align__(16) float sx[BLOCK_B][Tch * Msz];
    __shared__ __align__(16) float shp[2][BLOCK_B][20];    // h state, plain, dbl-buffered

    const int tid = threadIdx.x;
    const int j = tid % Hsz;
    const int y = tid / Hsz;
    const int b = blockIdx.x * BLOCK_B + y;
    const bool act = (b < Bsz);
    const int bb = act ? b : (Bsz - 1);

    // ---- W_ih into smem; sigmoid gates (i,f,o) pre-scaled by 0.5 ----
    for (int idx = tid; idx < Msz * Hsz; idx += NTHREADS) {
        int k = idx / Hsz, jj = idx % Hsz;
        ulonglong2 w2;
        w2.x = pk2(0.5f * Wih[jj * Msz + k],
                   0.5f * Wih[(Hsz + jj) * Msz + k]);
        w2.y = pk2(Wih[(2 * Hsz + jj) * Msz + k],
                   0.5f * Wih[(3 * Hsz + jj) * Msz + k]);
        wih_s[idx] = w2;
    }

    // ---- W_hh in registers: 8 natural pairs per gate + scalar k=16 column ----
    u64 wh0[8], wh1[8], wh2[8], wh3[8];
    float w16_0, w16_1, w16_2, w16_3;
    {
        const float* w0 = Whh + (0 * Hsz + j) * Hsz;
        const float* w1 = Whh + (1 * Hsz + j) * Hsz;
        const float* w2 = Whh + (2 * Hsz + j) * Hsz;
        const float* w3 = Whh + (3 * Hsz + j) * Hsz;
#pragma unroll
        for (int p = 0; p < 8; p++) {
            wh0[p] = pk2(0.5f * w0[2 * p], 0.5f * w0[2 * p + 1]);
            wh1[p] = pk2(0.5f * w1[2 * p], 0.5f * w1[2 * p + 1]);
            wh2[p] = pk2(w2[2 * p],        w2[2 * p + 1]);
            wh3[p] = pk2(0.5f * w3[2 * p], 0.5f * w3[2 * p + 1]);
        }
        w16_0 = 0.5f * w0[16];
        w16_1 = 0.5f * w1[16];
        w16_2 = w2[16];
        w16_3 = 0.5f * w3[16];
    }
    const u64 b_if = pk2(0.5f * (bih[j] + bhh[j]),
                         0.5f * (bih[Hsz + j] + bhh[Hsz + j]));
    const u64 b_go = pk2(bih[2 * Hsz + j] + bhh[2 * Hsz + j],
                         0.5f * (bih[3 * Hsz + j] + bhh[3 * Hsz + j]));

    const long OUT_ELEMS = (long)Bsz * Lsz * Hsz;
    const long H_OFF = OUT_ELEMS;
    const long C_OFF = OUT_ELEMS + (long)Bsz * Hsz;
    const long X_OFF = OUT_ELEMS + 2L * (long)Bsz * Hsz;

    const float4* xrow4 = (const float4*)(x + (long)bb * Lsz * Msz);
    float4*       xo4   = (float4*)(out + X_OFF + (long)bb * Lsz * Msz);
    float*        obase = out + (long)bb * Lsz * Hsz;

    shp[0][y][j] = 0.0f;
    shp[1][y][j] = 0.0f;
    float c = 0.0f, hn = 0.0f;

    // prefetch first x chunk: 2 float4 per thread (34 f4 per row-chunk)
    float4 v0 = xrow4[j];
    float4 v1 = xrow4[Msz + j];

    for (int ch = 0; ch < NCHUNK; ch++) {
        const int t0 = ch * Tch;

        // ---- stage chunk (v0,v1) + mirror to x passthrough ----
        if (act) {
            xo4[ch * CHUNK_F4 + j] = v0;
            xo4[ch * CHUNK_F4 + Msz + j] = v1;
        }
        {
            float f[8] = {v0.x, v0.y, v0.z, v0.w, v1.x, v1.y, v1.z, v1.w};
#pragma unroll
            for (int i = 0; i < 4; i++) {
                int fi = 4 * j + i;                 // chunk float index = t*17 + k
                int t = fi / Msz, k = fi - Msz * t;
                sx[y][k * Tch + t] = f[i];
            }
#pragma unroll
            for (int i = 0; i < 4; i++) {
                int fi = 68 + 4 * j + i;
                int t = fi / Msz, k = fi - Msz * t;
                sx[y][k * Tch + t] = f[4 + i];
            }
        }
        if (ch + 1 < NCHUNK) {
            v0 = xrow4[(ch + 1) * CHUNK_F4 + j];
            v1 = xrow4[(ch + 1) * CHUNK_F4 + Msz + j];
        }
        __syncthreads();

        // ---- 8-step x-projection burst: per k, 1 LDS.128 w + 2 LDS.128 x ----
        u64 a_if[Tch], a_go[Tch];
#pragma unroll
        for (int t = 0; t < Tch; t++) { a_if[t] = b_if; a_go[t] = b_go; }
#pragma unroll
        for (int k = 0; k < Msz; k++) {
            const ulonglong2 w2 = wih_s[k * Hsz + j];            // {if, go} pairs
            const float4 xa = *(const float4*)&sx[y][k * Tch];     // t0..t3
            const float4 xb = *(const float4*)&sx[y][k * Tch + 4]; // t4..t7
            const u64 d0 = pk2(xa.x, xa.x);
            const u64 d1 = pk2(xa.y, xa.y);
            const u64 d2 = pk2(xa.z, xa.z);
            const u64 d3 = pk2(xa.w, xa.w);
            const u64 d4 = pk2(xb.x, xb.x);
            const u64 d5 = pk2(xb.y, xb.y);
            const u64 d6 = pk2(xb.z, xb.z);
            const u64 d7 = pk2(xb.w, xb.w);
            ffma2(a_if[0], w2.x, d0); ffma2(a_go[0], w2.y, d0);
            ffma2(a_if[1], w2.x, d1); ffma2(a_go[1], w2.y, d1);
            ffma2(a_if[2], w2.x, d2); ffma2(a_go[2], w2.y, d2);
            ffma2(a_if[3], w2.x, d3); ffma2(a_go[3], w2.y, d3);
            ffma2(a_if[4], w2.x, d4); ffma2(a_go[4], w2.y, d4);
            ffma2(a_if[5], w2.x, d5); ffma2(a_go[5], w2.y, d5);
            ffma2(a_if[6], w2.x, d6); ffma2(a_go[6], w2.y, d6);
            ffma2(a_if[7], w2.x, d7); ffma2(a_go[7], w2.y, d7);
        }

        // ---- 8 recurrence steps: h via 4xLDS.128 + 1xLDS.32 ----
#pragma unroll
        for (int tl = 0; tl < Tch; tl++) {
            const int t = t0 + tl;
            const int cur = t & 1, nxt = cur ^ 1;

            const ulonglong2* hp2 = (const ulonglong2*)shp[cur][y];
            const ulonglong2 q0 = hp2[0];
            const ulonglong2 q1 = hp2[1];
            const ulonglong2 q2 = hp2[2];
            const ulonglong2 q3 = hp2[3];
            const float h16 = shp[cur][y][16];

            u64 hc0 = 0ULL, hc1 = 0ULL, hc2 = 0ULL, hc3 = 0ULL;
            ffma2(hc0, wh0[0], q0.x); ffma2(hc1, wh1[0], q0.x);
            ffma2(hc2, wh2[0], q0.x); ffma2(hc3, wh3[0], q0.x);
            ffma2(hc0, wh0[1], q0.y); ffma2(hc1, wh1[1], q0.y);
            ffma2(hc2, wh2[1], q0.y); ffma2(hc3, wh3[1], q0.y);
            ffma2(hc0, wh0[2], q1.x); ffma2(hc1, wh1[2], q1.x);
            ffma2(hc2, wh2[2], q1.x); ffma2(hc3, wh3[2], q1.x);
            ffma2(hc0, wh0[3], q1.y); ffma2(hc1, wh1[3], q1.y);
            ffma2(hc2, wh2[3], q1.y); ffma2(hc3, wh3[3], q1.y);
            ffma2(hc0, wh0[4], q2.x); ffma2(hc1, wh1[4], q2.x);
            ffma2(hc2, wh2[4], q2.x); ffma2(hc3, wh3[4], q2.x);
            ffma2(hc0, wh0[5], q2.y); ffma2(hc1, wh1[5], q2.y);
            ffma2(hc2, wh2[5], q2.y); ffma2(hc3, wh3[5], q2.y);
            ffma2(hc0, wh0[6], q3.x); ffma2(hc1, wh1[6], q3.x);
            ffma2(hc2, wh2[6], q3.x); ffma2(hc3, wh3[6], q3.x);
            ffma2(hc0, wh0[7], q3.y); ffma2(hc1, wh1[7], q3.y);
            ffma2(hc2, wh2[7], q3.y); ffma2(hc3, wh3[7], q3.y);

            float xi, xf_, xg, xo_;
            upk2(a_if[tl], xi, xf_);
            upk2(a_go[tl], xg, xo_);
            float l, h;
            upk2(hc0, l, h); const float zi = fmaf(w16_0, h16, xi  + (l + h));
            upk2(hc1, l, h); const float zf = fmaf(w16_1, h16, xf_ + (l + h));
            upk2(hc2, l, h); const float zg = fmaf(w16_2, h16, xg  + (l + h));
            upk2(hc3, l, h); const float zo = fmaf(w16_3, h16, xo_ + (l + h));

            const float ig = fmaf(0.5f, tanh_ap(zi), 0.5f);
            const float fg = fmaf(0.5f, tanh_ap(zf), 0.5f);
            const float gg = tanh_ap(zg);
            const float og = fmaf(0.5f, tanh_ap(zo), 0.5f);
            c  = fg * c + ig * gg;
            hn = og * tanh_ap(c);

            if (act) obase[t * Hsz + j] = hn;   // direct STG.32 (fire-and-forget)
            shp[nxt][y][j] = hn;
            __syncthreads();
        }
    }

    if (act) {
        out[H_OFF + (long)b * Hsz + j] = hn;
        out[C_OFF + (long)b * Hsz + j] = c;
    }
}

extern "C" void kernel_launch(void* const* d_in, const int* in_sizes, int n_in,
                              void* d_out, int out_size) {
    const float* x   = (const float*)d_in[0];
    const float* Wih = (const float*)d_in[1];
    const float* Whh = (const float*)d_in[2];
    const float* bih = (const float*)d_in[3];
    const float* bhh = (const float*)d_in[4];
    float* out = (float*)d_out;
    (void)in_sizes; (void)n_in; (void)out_size;

    lstm_fused_kernel<<<NBLOCKS, NTHREADS>>>(x, Wih, Whh, bih, bhh, out);
}